// round 1
// baseline (speedup 1.0000x reference)
#include <cuda_runtime.h>
#include <math.h>

// ---------------- problem constants ----------------
#define B_      32
#define C_IN    128
#define H_      64
#define W_      64
#define K_      8
#define C_OUT   128
#define HID     512      // C_IN * 4
#define HW      (H_*W_)  // 4096
#define PER_B_W (C_OUT*C_IN*9)  // 147456

// ---------------- scratch (device globals; no allocations) ----------------
__device__ float g_pooled[B_ * C_IN];
__device__ float g_alphas[B_ * K_];
__device__ float g_aggb[B_ * C_OUT];
__device__ float g_aggw[(size_t)B_ * PER_B_W];   // 18.9 MB

// ---------------- 1) global average pool ----------------
__global__ __launch_bounds__(256) void pool_kernel(const float* __restrict__ x,
                                                   float* __restrict__ pooled) {
    int bc = blockIdx.x;                 // 0 .. B*C_IN-1
    const float* p = x + (size_t)bc * HW;
    float s = 0.f;
    for (int i = threadIdx.x; i < HW; i += 256) s += p[i];
#pragma unroll
    for (int o = 16; o; o >>= 1) s += __shfl_xor_sync(0xffffffffu, s, o);
    __shared__ float red[8];
    if ((threadIdx.x & 31) == 0) red[threadIdx.x >> 5] = s;
    __syncthreads();
    if (threadIdx.x < 8) {
        s = red[threadIdx.x];
#pragma unroll
        for (int o = 4; o; o >>= 1) s += __shfl_xor_sync(0xffu, s, o);
        if (threadIdx.x == 0) pooled[bc] = s * (1.f / (float)HW);
    }
}

// ---------------- 2) attention MLP + softmax + agg bias ----------------
__global__ __launch_bounds__(512) void attn_kernel(const float* __restrict__ pooled,
                                                   const float* __restrict__ prompt,
                                                   const float* __restrict__ w1,
                                                   const float* __restrict__ b1,
                                                   const float* __restrict__ w2,
                                                   const float* __restrict__ b2,
                                                   const float* __restrict__ kbias,
                                                   float* __restrict__ alphas,
                                                   float* __restrict__ aggb) {
    int b = blockIdx.x;
    int t = threadIdx.x;
    __shared__ float sp[C_IN];
    __shared__ float sh[HID];
    __shared__ float ss[HID];
    __shared__ float sc[K_];
    __shared__ float sal[K_];

    if (t < C_IN) sp[t] = pooled[b * C_IN + t];
    __syncthreads();

    {   // h = relu(pooled @ w1^T + b1) ; w1 is (HID, C_IN)
        const float* wr = w1 + (size_t)t * C_IN;
        float acc = b1[t];
#pragma unroll 8
        for (int i = 0; i < C_IN; i++) acc = fmaf(sp[i], wr[i], acc);
        sh[t] = fmaxf(acc, 0.f);
    }
    __syncthreads();
    {   // s = h @ w2^T + b2 ; w2 is (HID, HID)
        const float* wr = w2 + (size_t)t * HID;
        float acc = b2[t];
#pragma unroll 8
        for (int i = 0; i < HID; i++) acc = fmaf(sh[i], wr[i], acc);
        ss[t] = acc;
    }
    __syncthreads();

    int wrp = t >> 5, lane = t & 31;
    if (wrp < K_) {   // scores[k] = dot(s, prompt[k])
        const float* pr = prompt + (size_t)wrp * HID;
        float acc = 0.f;
        for (int i = lane; i < HID; i += 32) acc = fmaf(ss[i], pr[i], acc);
#pragma unroll
        for (int o = 16; o; o >>= 1) acc += __shfl_xor_sync(0xffffffffu, acc, o);
        if (lane == 0) sc[wrp] = acc;
    }
    __syncthreads();

    if (t == 0) {   // softmax over K=8 (TEMPERATURE = 1)
        float m = sc[0];
#pragma unroll
        for (int k = 1; k < K_; k++) m = fmaxf(m, sc[k]);
        float e[K_], sum = 0.f;
#pragma unroll
        for (int k = 0; k < K_; k++) { e[k] = __expf(sc[k] - m); sum += e[k]; }
        float inv = 1.f / sum;
#pragma unroll
        for (int k = 0; k < K_; k++) { sal[k] = e[k] * inv; alphas[b * K_ + k] = sal[k]; }
    }
    __syncthreads();

    if (t < C_OUT) {   // agg_b = alphas @ kernels_bias
        float acc = 0.f;
#pragma unroll
        for (int k = 0; k < K_; k++) acc = fmaf(sal[k], kbias[k * C_OUT + t], acc);
        aggb[b * C_OUT + t] = acc;
    }
}

// ---------------- 3) aggregate conv weights per sample ----------------
__global__ __launch_bounds__(256) void aggw_kernel(const float* __restrict__ kw,
                                                   const float* __restrict__ alphas,
                                                   float* __restrict__ aggw) {
    int b = blockIdx.y;
    int i = blockIdx.x * 256 + threadIdx.x;   // 0 .. PER_B_W-1
    __shared__ float a[K_];
    if (threadIdx.x < K_) a[threadIdx.x] = alphas[b * K_ + threadIdx.x];
    __syncthreads();
    float acc = 0.f;
#pragma unroll
    for (int k = 0; k < K_; k++) acc = fmaf(a[k], kw[(size_t)k * PER_B_W + i], acc);
    aggw[(size_t)b * PER_B_W + i] = acc;
}

// ---------------- 4) per-sample 3x3 conv ----------------
// block: (b, oc_block of 32, 16x16 spatial tile); 256 threads
// thread: 2x2 pixel quad  x  8 output channels -> 32 fp32 accumulators
#define TH 16
#define TW 16
#define CI_CHUNK 16
#define OC_BLK 32
#define IN_PITCH 20          // 18 cols padded
#define IN_TILE (CI_CHUNK * 18 * IN_PITCH)   // 5760 floats
#define W_TILE  (OC_BLK * CI_CHUNK * 9)      // 4608 floats

__global__ __launch_bounds__(256, 2) void conv_kernel(const float* __restrict__ x,
                                                      const float* __restrict__ aggw,
                                                      const float* __restrict__ aggb,
                                                      float* __restrict__ out) {
    __shared__ float in_s[IN_TILE];
    __shared__ float w_s[W_TILE];

    const int b    = blockIdx.z;
    const int ocb  = blockIdx.y;            // 0..3
    const int tile = blockIdx.x;            // 0..15
    const int tx   = tile & 3, ty = tile >> 2;
    const int tid  = threadIdx.x;
    const int oc_sub = tid >> 6;            // 0..3
    const int slot   = tid & 63;            // 0..63
    const int qx = slot & 7, qy = slot >> 3;
    const int py = qy * 2, px = qx * 2;     // pixel base within tile

    const int gy0 = ty * TH - 1;            // input tile origin (with halo)
    const int gx0 = tx * TW - 1;

    float acc[8][4];
#pragma unroll
    for (int j = 0; j < 8; j++)
#pragma unroll
        for (int p = 0; p < 4; p++) acc[j][p] = 0.f;

    const float* xb = x + (size_t)b * C_IN * HW;
    const float* wb = aggw + (size_t)b * PER_B_W + (size_t)(ocb * OC_BLK) * (C_IN * 9);

    for (int ci0 = 0; ci0 < C_IN; ci0 += CI_CHUNK) {
        // ---- stage input tile: CI_CHUNK x 18 x 18 (zero-padded halo) ----
        for (int idx = tid; idx < CI_CHUNK * 18 * 18; idx += 256) {
            int ci  = idx / (18 * 18);
            int rem = idx - ci * (18 * 18);
            int iy  = rem / 18;
            int ix  = rem - iy * 18;
            int gy = gy0 + iy, gx = gx0 + ix;
            float v = 0.f;
            if ((unsigned)gy < H_ && (unsigned)gx < W_)
                v = xb[((size_t)(ci0 + ci) * H_ + gy) * W_ + gx];
            in_s[ci * (18 * IN_PITCH) + iy * IN_PITCH + ix] = v;
        }
        // ---- stage weights: OC_BLK x CI_CHUNK x 9 ----
        for (int idx = tid; idx < W_TILE; idx += 256) {
            int oc  = idx / (CI_CHUNK * 9);
            int rem = idx - oc * (CI_CHUNK * 9);     // ci*9 + tap
            w_s[idx] = wb[(size_t)oc * (C_IN * 9) + (size_t)ci0 * 9 + rem];
        }
        __syncthreads();

#pragma unroll 1
        for (int ci = 0; ci < CI_CHUNK; ci++) {
            float win[4][4];
            const float* ip = &in_s[ci * (18 * IN_PITCH) + py * IN_PITCH + px];
#pragma unroll
            for (int yy = 0; yy < 4; yy++)
#pragma unroll
                for (int xx = 0; xx < 4; xx++)
                    win[yy][xx] = ip[yy * IN_PITCH + xx];

#pragma unroll
            for (int j = 0; j < 8; j++) {
                const float* wp = &w_s[(oc_sub * 8 + j) * (CI_CHUNK * 9) + ci * 9];
#pragma unroll
                for (int dy = 0; dy < 3; dy++)
#pragma unroll
                    for (int dx = 0; dx < 3; dx++) {
                        float w = wp[dy * 3 + dx];
                        acc[j][0] = fmaf(w, win[dy][dx],         acc[j][0]);
                        acc[j][1] = fmaf(w, win[dy][dx + 1],     acc[j][1]);
                        acc[j][2] = fmaf(w, win[dy + 1][dx],     acc[j][2]);
                        acc[j][3] = fmaf(w, win[dy + 1][dx + 1], acc[j][3]);
                    }
            }
        }
        __syncthreads();
    }

    // ---- epilogue: add bias, store ----
    const int y0 = ty * TH + py;
    const int x0 = tx * TW + px;
#pragma unroll
    for (int j = 0; j < 8; j++) {
        int oc = ocb * OC_BLK + oc_sub * 8 + j;
        float bias = aggb[b * C_OUT + oc];
        float* op = out + (((size_t)b * C_OUT + oc) * H_ + y0) * W_ + x0;
        op[0]      = acc[j][0] + bias;
        op[1]      = acc[j][1] + bias;
        op[W_]     = acc[j][2] + bias;
        op[W_ + 1] = acc[j][3] + bias;
    }
}

// ---------------- launch ----------------
extern "C" void kernel_launch(void* const* d_in, const int* in_sizes, int n_in,
                              void* d_out, int out_size) {
    const float* x      = (const float*)d_in[0];
    const float* prompt = (const float*)d_in[1];
    const float* w1     = (const float*)d_in[2];
    const float* b1     = (const float*)d_in[3];
    const float* w2     = (const float*)d_in[4];
    const float* b2     = (const float*)d_in[5];
    const float* kw     = (const float*)d_in[6];
    const float* kbias  = (const float*)d_in[7];
    float* out = (float*)d_out;

    float *pooled, *alphas, *aggb, *aggw;
    cudaGetSymbolAddress((void**)&pooled, g_pooled);
    cudaGetSymbolAddress((void**)&alphas, g_alphas);
    cudaGetSymbolAddress((void**)&aggb,   g_aggb);
    cudaGetSymbolAddress((void**)&aggw,   g_aggw);

    pool_kernel<<<B_ * C_IN, 256>>>(x, pooled);
    attn_kernel<<<B_, 512>>>(pooled, prompt, w1, b1, w2, b2, kbias, alphas, aggb);
    aggw_kernel<<<dim3(PER_B_W / 256, B_), 256>>>(kw, alphas, aggw);
    conv_kernel<<<dim3(16, C_OUT / OC_BLK, B_), 256>>>(x, aggw, aggb, out);
}